// round 13
// baseline (speedup 1.0000x reference)
#include <cuda_runtime.h>

#define B_   32
#define M_   64
#define A_   8400
#define TK   9
#define NC   80
#define EPSF 1e-9f

// Scratch (allocation-free). Packed per-anchor tag: bits[31:16] = positive
// count, bits[15:0] = sum of (m+1). count<=64, sum(m+1)<=4096 -> no overflow
// between fields; when count==1 the low half is exactly m+1.
// INVARIANT: zero at module load (CUDA zero-init); the sparse-assign kernel
// re-zeroes each nonzero element after consuming it, so every graph replay
// starts from zero.
__device__ int g_tag[B_ * A_];

__device__ __forceinline__ float iou_box(float gx1, float gy1, float gx2, float gy2,
                                         float bx1, float by1, float bx2, float by2) {
    // matches reference _iou: b1 = gt, b2 = other; denom = a1 + a2 - overlap + EPS
    float ix1 = fmaxf(gx1, bx1), iy1 = fmaxf(gy1, by1);
    float ix2 = fminf(gx2, bx2), iy2 = fminf(gy2, by2);
    float ov  = fmaxf(ix2 - ix1, 0.f) * fmaxf(iy2 - iy1, 0.f);
    float a1  = fmaxf(gx2 - gx1, 0.f) * fmaxf(gy2 - gy1, 0.f);
    float a2  = fmaxf(bx2 - bx1, 0.f) * fmaxf(by2 - by1, 0.f);
    return ov / (a1 + a2 - ov + EPSF);
}

// Output layout (float32): [0, B*A) labels | [B*A, B*A*5) bboxes | scores.
#define OFF1  (B_ * A_)            //  268,800  (fits int32 throughout)
#define OFF2  (B_ * A_ * 5)        // 1,344,000
#define NS4   ((B_ * A_ * NC) / 4) // 5,376,000 score float4s
#define NL4   ((B_ * A_) / 4)      //    67,200 label float4s

// Kernel 1: topk (blocks 0..255, bit-identical to the R12 passing kernel)
// overlapped with the default-fill of the ENTIRE output (blocks 256..2303):
// scores = 0, labels = bg, bboxes = gt[b][0] (the asg=0 default). The fill is
// GT-assignment-independent, so it runs concurrently with topk in one launch.
__global__ void __launch_bounds__(256) atss_topk_fill_kernel(
    const float* __restrict__ anchors,    // [A,4]
    const float* __restrict__ gt_bboxes,  // [B,M,4]
    const float* __restrict__ pad_mask,   // [B,M,1]
    const int*   __restrict__ bg_ptr,     // [1] or null
    float*       __restrict__ out)
{
    const int t = threadIdx.x;

    if (blockIdx.x >= 256) {
        // ---------------- fill branch: pure streaming stores ----------------
        const int tid    = (blockIdx.x - 256) * 256 + t;   // 0 .. 524287
        const int stride = 2048 * 256;

        float4* s4 = (float4*)(out + OFF2);
        const float4 z = make_float4(0.f, 0.f, 0.f, 0.f);
        for (int i = tid; i < NS4; i += stride) s4[i] = z;

        const float bgf = (float)(bg_ptr ? bg_ptr[0] : NC);
        const float4 lv = make_float4(bgf, bgf, bgf, bgf);
        float4* l4 = (float4*)out;
        for (int i = tid; i < NL4; i += stride) l4[i] = lv;

        float4* b4 = (float4*)(out + OFF1);
        for (int i = tid; i < B_ * A_; i += stride) {
            const int b = i / A_;
            b4[i] = ((const float4*)gt_bboxes)[b * M_];    // gt[b][0] default
        }
        return;
    }

    // ---------------- topk branch (one warp per (b,m)) ----------------
    const int warp = t >> 5;
    const int lane = t & 31;
    const int wid  = blockIdx.x * 8 + warp;   // (b,m) flat, 2048 total
    const int b = wid >> 6;
    const int m = wid & 63;

    if (pad_mask[wid] <= 0.f) return;         // warp-uniform

    const float4 g = ((const float4*)gt_bboxes)[wid];
    const float gcx = (g.x + g.z) * 0.5f;
    const float gcy = (g.y + g.w) * 0.5f;

    const int   FS[3]   = {80, 40, 20};
    const float INV[3]  = {0.125f, 0.0625f, 0.03125f};  // 1/stride (exact pow2)
    const int   BASE[3] = {0, 6400, 8000};

    int my_win = 0;          // lane r (< 27) ends up holding winner lvl*9 + r
    bool have_win = false;

    #pragma unroll
    for (int lvl = 0; lvl < 3; lvl++) {
        const int fs = FS[lvl];
        const int base = BASE[lvl];
        int jx0 = (int)floorf(gcx * INV[lvl] - 0.5f) - 2;
        int iy0 = (int)floorf(gcy * INV[lvl] - 0.5f) - 2;
        jx0 = min(max(jx0, 0), fs - 5);
        iy0 = min(max(iy0, 0), fs - 5);

        unsigned long long key = ~0ull;
        if (lane < 25) {
            const int idx = base + (iy0 + lane / 5) * fs + (jx0 + lane % 5);
            float4 ab = ((const float4*)anchors)[idx];
            float acx = (ab.x + ab.z) * 0.5f;
            float acy = (ab.y + ab.w) * 0.5f;
            float dx = gcx - acx, dy = gcy - acy;
            float d2 = dx * dx + dy * dy;       // nonneg -> bit pattern is order-preserving
            key = ((unsigned long long)__float_as_uint(d2) << 32) | (unsigned)idx;
        }

        #pragma unroll
        for (int r = 0; r < TK; r++) {
            unsigned long long mn = key;
            #pragma unroll
            for (int off = 16; off; off >>= 1) {
                unsigned long long o = __shfl_xor_sync(0xffffffffu, mn, off);
                if (o < mn) mn = o;
            }
            if (key == mn) key = ~0ull;         // winner drops out (keys unique)
            if (lane == lvl * TK + r) { my_win = (int)(mn & 0xffffffffu); have_win = true; }
        }
    }

    float my_iou = 0.f;
    float4 ab = make_float4(0.f, 0.f, 0.f, 0.f);
    if (have_win) {
        ab = ((const float4*)anchors)[my_win];
        my_iou = iou_box(g.x, g.y, g.z, g.w, ab.x, ab.y, ab.z, ab.w);
    }

    // mean + std (ddof=1), sequential order r = 0..26 (bit-identical to R12)
    float mean = 0.f;
    #pragma unroll
    for (int r = 0; r < 27; r++) mean += __shfl_sync(0xffffffffu, my_iou, r);
    mean *= (1.f / 27.f);
    float var = 0.f;
    #pragma unroll
    for (int r = 0; r < 27; r++) {
        float v = __shfl_sync(0xffffffffu, my_iou, r) - mean;
        var += v * v;
    }
    const float thr = mean + sqrtf(var * (1.f / 26.f));

    if (have_win && my_iou > thr) {
        float acx = (ab.x + ab.z) * 0.5f;
        float acy = (ab.y + ab.w) * 0.5f;
        float lmin = fminf(fminf(acx - g.x, acy - g.y), fminf(g.z - acx, g.w - acy));
        if (lmin > EPSF) {                      // is_in_gts (strict > EPS)
            atomicAdd(&g_tag[b * A_ + my_win], 0x10000 + m + 1);
        }
    }
}

// Kernel 2: sparse assign. Negatives were fully prefilled by kernel 1, so a
// warp with no positive lanes does one coalesced tag load + ballot and exits.
// Positives: warp-cooperative conflict resolution (64-GT IoU argmax via u64
// key min-reduce; key = (~iou_bits, m) == first-max-over-m, bit-identical to
// R12), then overwrite label + bbox + one score element.
__global__ void __launch_bounds__(256) atss_assign_kernel(
    const float* __restrict__ anchors,    // [A,4]
    const int*   __restrict__ gt_labels,  // [B,M]
    const float* __restrict__ gt_bboxes,  // [B,M,4]
    const float* __restrict__ pred,       // [B,A,4]
    float*       __restrict__ out)
{
    const int b    = blockIdx.y;
    const int t    = threadIdx.x;
    const int lane = t & 31;
    const int a    = blockIdx.x * 256 + t;
    const bool valid = a < A_;

    __shared__ float4 s_gt[M_];
    __shared__ int    s_lab[M_];
    if (t < M_) {
        s_gt[t]  = ((const float4*)gt_bboxes)[b * M_ + t];
        s_lab[t] = gt_labels[b * M_ + t];
    }
    __syncthreads();

    const int ba = b * A_ + a;
    int tag = 0;
    if (valid) {
        tag = g_tag[ba];
        if (tag) g_tag[ba] = 0;     // restore zero invariant for next replay
    }
    const int cnt = tag >> 16;
    int asg = (cnt == 1) ? (tag & 0xffff) - 1 : 0;

    // warp-cooperative resolution of conflicted anchors (cnt > 1)
    unsigned conf = __ballot_sync(0xffffffffu, cnt > 1);
    const int wbase = a - lane;                    // anchor of lane 0 in this warp
    while (conf) {
        const int src = __ffs(conf) - 1;
        conf &= conf - 1;
        const float4 abx = ((const float4*)anchors)[wbase + src];  // uniform -> broadcast
        float4 g1 = s_gt[lane];
        float v1 = iou_box(g1.x, g1.y, g1.z, g1.w, abx.x, abx.y, abx.z, abx.w);
        float4 g2 = s_gt[lane + 32];
        float v2 = iou_box(g2.x, g2.y, g2.z, g2.w, abx.x, abx.y, abx.z, abx.w);
        // key = (~iou_bits, m): min key == (max iou, first m). iou >= +0.0 so
        // float bits are order-preserving and bit-equality == value-equality.
        unsigned long long k1 = ((unsigned long long)(~__float_as_uint(v1)) << 32) | (unsigned)lane;
        unsigned long long k2 = ((unsigned long long)(~__float_as_uint(v2)) << 32) | (unsigned)(lane + 32);
        unsigned long long k = (k2 < k1) ? k2 : k1;
        #pragma unroll
        for (int off = 16; off; off >>= 1) {
            unsigned long long o = __shfl_xor_sync(0xffffffffu, k, off);
            if (o < k) k = o;
        }
        if (lane == src) asg = (int)(k & 0xffffffffu);
    }

    if (valid && cnt > 0) {
        const int   label = s_lab[asg];
        const float4 p  = ((const float4*)pred)[ba];
        const float4 gg = s_gt[asg];
        const float sval = iou_box(gg.x, gg.y, gg.z, gg.w, p.x, p.y, p.z, p.w);

        out[ba] = (float)label;                  // overwrite prefilled bg
        ((float4*)(out + OFF1))[ba] = gg;        // overwrite prefilled gt[b][0]
        if (label >= 0 && label < NC)
            out[OFF2 + ba * NC + label] = sval;  // one-hot * max(pious)
    }
}

extern "C" void kernel_launch(void* const* d_in, const int* in_sizes, int n_in,
                              void* d_out, int out_size) {
    const float* anchors   = (const float*)d_in[0];
    const int*   gt_labels = (const int*)d_in[1];
    const float* gt_bboxes = (const float*)d_in[2];
    const float* pad_mask  = (const float*)d_in[3];
    const float* pred      = (const float*)d_in[4];
    const int*   bg_ptr    = (n_in > 5) ? (const int*)d_in[5] : nullptr;
    float* out = (float*)d_out;

    atss_topk_fill_kernel<<<2304, 256>>>(anchors, gt_bboxes, pad_mask, bg_ptr, out);
    atss_assign_kernel<<<dim3((A_ + 255) / 256, B_), 256>>>(
        anchors, gt_labels, gt_bboxes, pred, out);
}